// round 8
// baseline (speedup 1.0000x reference)
#include <cuda_runtime.h>
#include <cuda_bf16.h>

// Table-batched EmbeddingBag forward (SUM pooling).
// T=8 tables, B=8192 batch, D=128 dim, ROWS=200000 rows/table.
// One warp per bag; lane l owns one float4 of the D=128 row (512B
// coalesced gather per row). Indices fetched as int4 chunks (broadcast
// LDG.128), software-pipelined one chunk ahead of the row gathers,
// with the final iteration peeled (no ternary in the hot loop).

#ifndef EMB_T
#define EMB_T 8
#define EMB_B 8192
#define EMB_D 128
#define EMB_ROWS 200000
#endif

#define D4 (EMB_D / 4)   // float4 per row = 32

__device__ __forceinline__ void facc(float4& a, const float4& v) {
    a.x += v.x; a.y += v.y; a.z += v.z; a.w += v.w;
}

__device__ __forceinline__ void gather4(
    const float4* __restrict__ tbl, int4 idx, float4& a0, float4& a1)
{
    const float4 v0 = __ldg(tbl + (size_t)idx.x * D4);
    const float4 v1 = __ldg(tbl + (size_t)idx.y * D4);
    const float4 v2 = __ldg(tbl + (size_t)idx.z * D4);
    const float4 v3 = __ldg(tbl + (size_t)idx.w * D4);
    facc(a0, v0); facc(a1, v1); facc(a0, v2); facc(a1, v3);
}

__global__ __launch_bounds__(256) void emb_bag_sum_kernel(
    const int* __restrict__ indices,
    const int* __restrict__ offsets,
    const float4* __restrict__ weights4,
    float4* __restrict__ out4,
    int n_bags)
{
    const int warp_id = (blockIdx.x * blockDim.x + threadIdx.x) >> 5;
    const int lane    = threadIdx.x & 31;
    if (warp_id >= n_bags) return;

    const int bag     = warp_id;
    const int feature = bag / EMB_B;
    const int b       = bag - feature * EMB_B;

    const int start = __ldg(offsets + bag);
    const int end   = __ldg(offsets + bag + 1);
    const int n     = end - start;

    // Per-table base, shifted by this lane's float4 within the row.
    const float4* __restrict__ tbl =
        weights4 + (size_t)feature * EMB_ROWS * D4 + lane;

    float4 a0 = make_float4(0.f, 0.f, 0.f, 0.f);
    float4 a1 = make_float4(0.f, 0.f, 0.f, 0.f);

    // Fast path: 16B-aligned index run, multiple of 4 (L=20 -> always).
    if ((n & 3) == 0 && ((start & 3) == 0) && n > 0) {
        const int4* __restrict__ idx4 = (const int4*)(indices + start);
        const int nchunks = n >> 2;

        int4 cur = __ldg(idx4);
        // Pipelined body: prefetch chunk c+1 while gathering chunk c.
        for (int c = 0; c + 1 < nchunks; ++c) {
            const int4 nxt = __ldg(idx4 + c + 1);
            gather4(tbl, cur, a0, a1);
            cur = nxt;
        }
        // Peeled last chunk.
        gather4(tbl, cur, a0, a1);
    } else {
        // Generic ragged fallback.
        #pragma unroll 4
        for (int j = start; j < end; ++j) {
            const int r = __ldg(indices + j);
            facc(a0, __ldg(tbl + (size_t)r * D4));
        }
    }

    facc(a0, a1);

    const size_t o = (size_t)b * (EMB_T * D4) + (size_t)feature * D4 + lane;
    out4[o] = a0;
}

extern "C" void kernel_launch(void* const* d_in, const int* in_sizes, int n_in,
                              void* d_out, int out_size)
{
    const int*   indices = (const int*)d_in[0];
    const int*   offsets = (const int*)d_in[1];
    const float* weights = (const float*)d_in[2];

    const int n_bags = in_sizes[1] - 1;      // T*B
    const int warps_per_block = 256 / 32;
    const int blocks = (n_bags + warps_per_block - 1) / warps_per_block;

    emb_bag_sum_kernel<<<blocks, 256>>>(
        indices, offsets,
        (const float4*)weights, (float4*)d_out, n_bags);
}

// round 9
// speedup vs baseline: 1.0468x; 1.0468x over previous
#include <cuda_runtime.h>
#include <cuda_bf16.h>

// Table-batched EmbeddingBag forward (SUM pooling).
// T=8 tables, B=8192 batch, D=128 dim, ROWS=200000 rows/table.
// One warp per bag; lane l owns one float4 of the D=128 row (512B
// coalesced gather per row). Bag indices staged through shared memory
// (one coalesced LDG per chunk, broadcast LDS in the hot loop).
// __launch_bounds__(256,8) pins regs<=32 so occupancy stays at 100%
// theoretical — the empirical driver of DRAM efficiency here.

#ifndef EMB_T
#define EMB_T 8
#define EMB_B 8192
#define EMB_D 128
#define EMB_ROWS 200000
#endif

#define D4 (EMB_D / 4)          // float4 per row = 32
#define WARPS_PER_BLOCK 8
#define STAGE 32                // indices staged per chunk

__device__ __forceinline__ void facc(float4& a, const float4& v) {
    a.x += v.x; a.y += v.y; a.z += v.z; a.w += v.w;
}

__global__ __launch_bounds__(256, 8) void emb_bag_sum_kernel(
    const int* __restrict__ indices,
    const int* __restrict__ offsets,
    const float4* __restrict__ weights4,
    float4* __restrict__ out4,
    int n_bags)
{
    __shared__ int sidx[WARPS_PER_BLOCK][STAGE];

    const int warp_id = (blockIdx.x * blockDim.x + threadIdx.x) >> 5;
    const int w       = (threadIdx.x >> 5);
    const int lane    = threadIdx.x & 31;
    if (warp_id >= n_bags) return;

    const int bag     = warp_id;
    const int feature = bag / EMB_B;
    const int b       = bag - feature * EMB_B;

    const int start = __ldg(offsets + bag);
    const int end   = __ldg(offsets + bag + 1);

    // Per-table base, shifted by this lane's float4 within the row.
    const float4* __restrict__ tbl =
        weights4 + (size_t)feature * EMB_ROWS * D4 + lane;

    float4 a0 = make_float4(0.f, 0.f, 0.f, 0.f);
    float4 a1 = make_float4(0.f, 0.f, 0.f, 0.f);

    int pos = start;
    while (pos < end) {
        const int rem = end - pos;
        const int m   = rem < STAGE ? rem : STAGE;

        // One coalesced index load per chunk (L=20 -> single chunk).
        if (lane < m) sidx[w][lane] = __ldg(indices + pos + lane);
        __syncwarp();

        int j = 0;
        for (; j + 4 <= m; j += 4) {
            const int r0 = sidx[w][j + 0];
            const int r1 = sidx[w][j + 1];
            const int r2 = sidx[w][j + 2];
            const int r3 = sidx[w][j + 3];
            const float4 v0 = __ldg(tbl + (size_t)r0 * D4);
            const float4 v1 = __ldg(tbl + (size_t)r1 * D4);
            const float4 v2 = __ldg(tbl + (size_t)r2 * D4);
            const float4 v3 = __ldg(tbl + (size_t)r3 * D4);
            facc(a0, v0); facc(a1, v1); facc(a0, v2); facc(a1, v3);
        }
        for (; j < m; ++j) {
            const int r = sidx[w][j];
            facc(a0, __ldg(tbl + (size_t)r * D4));
        }
        __syncwarp();       // protect sidx before next chunk overwrite
        pos += m;
    }

    facc(a0, a1);

    const size_t o = (size_t)b * (EMB_T * D4) + (size_t)feature * D4 + lane;
    out4[o] = a0;
}

extern "C" void kernel_launch(void* const* d_in, const int* in_sizes, int n_in,
                              void* d_out, int out_size)
{
    const int*   indices = (const int*)d_in[0];
    const int*   offsets = (const int*)d_in[1];
    const float* weights = (const float*)d_in[2];

    const int n_bags = in_sizes[1] - 1;      // T*B
    const int blocks = (n_bags + WARPS_PER_BLOCK - 1) / WARPS_PER_BLOCK;

    emb_bag_sum_kernel<<<blocks, 256>>>(
        indices, offsets,
        (const float4*)weights, (float4*)d_out, n_bags);
}

// round 10
// speedup vs baseline: 1.0480x; 1.0011x over previous
#include <cuda_runtime.h>
#include <cuda_bf16.h>

// Table-batched EmbeddingBag forward (SUM pooling).
// T=8 tables, B=8192 batch, D=128 dim, ROWS=200000 rows/table.
// Persistent grid-stride kernel: one wave of 148x8 CTAs; each warp
// processes ~7 bags. One warp per bag; lane l owns one float4 of the
// D=128 row (512B coalesced gather per row). Simple dependent gather
// loop (empirically best: DRAM% tracks occupancy, not per-warp MLP).

#ifndef EMB_T
#define EMB_T 8
#define EMB_B 8192
#define EMB_D 128
#define EMB_ROWS 200000
#endif

#define D4 (EMB_D / 4)          // float4 per row = 32
#define NUM_SMS 148
#define BLOCKS_PER_SM 8

__device__ __forceinline__ void facc(float4& a, const float4& v) {
    a.x += v.x; a.y += v.y; a.z += v.z; a.w += v.w;
}

__global__ __launch_bounds__(256, 8) void emb_bag_sum_kernel(
    const int* __restrict__ indices,
    const int* __restrict__ offsets,
    const float4* __restrict__ weights4,
    float4* __restrict__ out4,
    int n_bags)
{
    const int lane        = threadIdx.x & 31;
    const int warp_global = (blockIdx.x * blockDim.x + threadIdx.x) >> 5;
    const int warp_stride = (gridDim.x * blockDim.x) >> 5;

    for (int bag = warp_global; bag < n_bags; bag += warp_stride) {
        const int feature = bag / EMB_B;
        const int b       = bag - feature * EMB_B;

        const int start = __ldg(offsets + bag);
        const int end   = __ldg(offsets + bag + 1);

        const float4* __restrict__ tbl =
            weights4 + (size_t)feature * EMB_ROWS * D4 + lane;

        float4 a0 = make_float4(0.f, 0.f, 0.f, 0.f);
        float4 a1 = make_float4(0.f, 0.f, 0.f, 0.f);

        int j = start;
        for (; j + 4 <= end; j += 4) {
            const int r0 = __ldg(indices + j + 0);
            const int r1 = __ldg(indices + j + 1);
            const int r2 = __ldg(indices + j + 2);
            const int r3 = __ldg(indices + j + 3);
            const float4 v0 = __ldg(tbl + (size_t)r0 * D4);
            const float4 v1 = __ldg(tbl + (size_t)r1 * D4);
            const float4 v2 = __ldg(tbl + (size_t)r2 * D4);
            const float4 v3 = __ldg(tbl + (size_t)r3 * D4);
            facc(a0, v0); facc(a1, v1); facc(a0, v2); facc(a1, v3);
        }
        for (; j < end; ++j) {
            const int r = __ldg(indices + j);
            facc(a0, __ldg(tbl + (size_t)r * D4));
        }

        facc(a0, a1);

        const size_t o = (size_t)b * (EMB_T * D4)
                       + (size_t)feature * D4 + lane;
        out4[o] = a0;
    }
}

extern "C" void kernel_launch(void* const* d_in, const int* in_sizes, int n_in,
                              void* d_out, int out_size)
{
    const int*   indices = (const int*)d_in[0];
    const int*   offsets = (const int*)d_in[1];
    const float* weights = (const float*)d_in[2];

    const int n_bags = in_sizes[1] - 1;      // T*B
    int blocks = NUM_SMS * BLOCKS_PER_SM;    // one resident wave
    const int max_blocks = (n_bags + 7) / 8; // never launch idle blocks
    if (blocks > max_blocks) blocks = max_blocks;

    emb_bag_sum_kernel<<<blocks, 256>>>(
        indices, offsets,
        (const float4*)weights, (float4*)d_out, n_bags);
}